// round 5
// baseline (speedup 1.0000x reference)
#include <cuda_runtime.h>
#include <cuda_fp16.h>
#include <cuda_bf16.h>
#include <cstdint>

// Problem constants
#define B_  8
#define N_  512
#define M_  32
#define HA  128
#define HB  64
#define C_  256          // 2*HA
#define BN_ROWS 4096     // B*N
#define ROWS 131072      // B*N*M
#define EPS 1e-5f

// ---------------- scratch ----------------
__device__ float    d_S  [BN_ROWS * C_];      // self projection  [4096][256]
__device__ float    d_P2 [BN_ROWS * C_];      // gather projection [4096][256]
__device__ unsigned d_gated2u[(size_t)ROWS * HA]; // half2(g_j, g_{j+128}) 64 MB
__device__ float    d_nbr[BN_ROWS * HA];
__device__ float    d_stats1[512];            // sum[0:256], sumsq[256:512]
__device__ float    d_stats2[256];            // sum[0:128], sumsq[128:256]
// bf16 hi/lo weight images (built by kP)
__device__ __nv_bfloat16 d_W3h[256 * 64];     // edge weights  W[:,256:320]
__device__ __nv_bfloat16 d_W3l[256 * 64];
__device__ __nv_bfloat16 d_Wabh[512 * 128];   // rows 0..255: W[:,0:128]; 256..511: W[:,128:256]
__device__ __nv_bfloat16 d_Wabl[512 * 128];

// ---------------- helpers ----------------
__device__ __forceinline__ unsigned packbf(float a, float b) {
    __nv_bfloat162 t = __floats2bfloat162_rn(a, b);   // x=a (low), y=b
    return *reinterpret_cast<unsigned*>(&t);
}
__device__ __forceinline__ unsigned packh(float a, float b) {
    __half2 t = __floats2half2_rn(a, b);              // x=a (low), y=b
    return *reinterpret_cast<unsigned*>(&t);
}

// mma.sync m16n8k16 row.col f32.bf16.bf16.f32 (sm_80+, legal on compute_100)
__device__ __forceinline__ void mma16816(float c[4],
                                         unsigned a0, unsigned a1, unsigned a2, unsigned a3,
                                         unsigned b0, unsigned b1) {
    asm volatile(
        "mma.sync.aligned.m16n8k16.row.col.f32.bf16.bf16.f32 "
        "{%0,%1,%2,%3}, {%4,%5,%6,%7}, {%8,%9}, {%0,%1,%2,%3};\n"
        : "+f"(c[0]), "+f"(c[1]), "+f"(c[2]), "+f"(c[3])
        : "r"(a0), "r"(a1), "r"(a2), "r"(a3), "r"(b0), "r"(b1));
}

// =====================================================================
// Kernel P: build bf16 hi/lo weight images; zero stat accumulators.
// =====================================================================
__global__ __launch_bounds__(256) void kP(const float* __restrict__ W) {
    const int ch = threadIdx.x;              // 0..255
    d_stats1[ch] = 0.f; d_stats1[ch + 256] = 0.f;
    if (ch < 128) { d_stats2[ch] = 0.f; d_stats2[ch + 128] = 0.f; }

    // W3 image: row ch = W[ch][256:320]
    const float* w3 = W + ch * 320 + 256;
#pragma unroll 4
    for (int k = 0; k < 64; k++) {
        float v = w3[k];
        __nv_bfloat16 h = __float2bfloat16_rn(v);
        d_W3h[ch * 64 + k] = h;
        d_W3l[ch * 64 + k] = __float2bfloat16_rn(v - __bfloat162float(h));
    }
    // Wab images: row ch = W[ch][0:128], row ch+256 = W[ch][128:256]
#pragma unroll
    for (int half = 0; half < 2; half++) {
        const float* src = W + ch * 320 + half * 128;
        __nv_bfloat16* dh = d_Wabh + (size_t)(ch + half * 256) * 128;
        __nv_bfloat16* dl = d_Wabl + (size_t)(ch + half * 256) * 128;
#pragma unroll 4
        for (int k = 0; k < 128; k++) {
            float v = src[k];
            __nv_bfloat16 h = __float2bfloat16_rn(v);
            dh[k] = h;
            dl[k] = __float2bfloat16_rn(v - __bfloat162float(h));
        }
    }
}

// =====================================================================
// Kernel A (tensor): S = X @ W1^T, P2 = X @ W2^T via bf16x3 mma.sync.
// Grid 64: bx = col half (0 -> d_S, 1 -> d_P2), by = row tile (128 rows).
// Per CTA: M=128, N=256, K=128. 256 threads / 8 warps (16 rows each).
// =====================================================================
#define KA_XST 136
#define KA_SM_XH 0
#define KA_SM_XL (KA_SM_XH + 128 * KA_XST * 2)      // 34816
#define KA_SM_BH (KA_SM_XL + 128 * KA_XST * 2)      // 69632
#define KA_SM_BL (KA_SM_BH + 256 * KA_XST * 2)      // 139264
#define KA_SMEM  (KA_SM_BL + 256 * KA_XST * 2)      // 208896

__global__ __launch_bounds__(256) void kA(const float* __restrict__ X) {
    extern __shared__ char sm[];
    const int tid = threadIdx.x;
    const int w   = tid >> 5, lane = tid & 31;
    const int gid = lane >> 2, tq = lane & 3;
    const int bx  = blockIdx.x & 1;
    const int by  = blockIdx.x >> 1;
    const int row0 = by * 128;
    const int c0   = bx * 256;

    // load + convert X rows [row0, row0+128)
    {
        const float4* xs = (const float4*)(X + (size_t)row0 * 128);
#pragma unroll
        for (int i = 0; i < 16; i++) {
            const int idx = tid + i * 256;           // 0..4095
            float4 v = xs[idx];
            const int r = idx >> 5, k4 = (idx & 31) * 4;
            float h0 = __bfloat162float(__float2bfloat16_rn(v.x));
            float h1 = __bfloat162float(__float2bfloat16_rn(v.y));
            float h2 = __bfloat162float(__float2bfloat16_rn(v.z));
            float h3 = __bfloat162float(__float2bfloat16_rn(v.w));
            uint2 hu, lu;
            hu.x = packbf(v.x, v.y);           hu.y = packbf(v.z, v.w);
            lu.x = packbf(v.x - h0, v.y - h1); lu.y = packbf(v.z - h2, v.w - h3);
            *(uint2*)(sm + KA_SM_XH + (r * KA_XST + k4) * 2) = hu;
            *(uint2*)(sm + KA_SM_XL + (r * KA_XST + k4) * 2) = lu;
        }
    }
    // copy weight image rows [c0, c0+256)
    {
        const uint4* sh = (const uint4*)(d_Wabh + (size_t)c0 * 128);
        const uint4* sl = (const uint4*)(d_Wabl + (size_t)c0 * 128);
#pragma unroll
        for (int i = 0; i < 16; i++) {
            const int idx = tid + i * 256;           // 0..4095 (16 uint4 per row)
            const int r = idx >> 4, q = idx & 15;
            *(uint4*)(sm + KA_SM_BH + r * (KA_XST * 2) + q * 16) = sh[idx];
            *(uint4*)(sm + KA_SM_BL + r * (KA_XST * 2) + q * 16) = sl[idx];
        }
    }
    __syncthreads();

    float acc[32][4];
#pragma unroll
    for (int nt = 0; nt < 32; nt++)
#pragma unroll
        for (int q = 0; q < 4; q++) acc[nt][q] = 0.f;

    const int rA = w * 16 + gid;
#pragma unroll
    for (int p = 0; p < 3; p++) {
        const char* A  = sm + (p == 2 ? KA_SM_XL : KA_SM_XH);
        const char* Bp = sm + (p == 1 ? KA_SM_BL : KA_SM_BH);
#pragma unroll
        for (int ks = 0; ks < 8; ks++) {
            const int k0 = ks * 16;
            unsigned a0 = *(const unsigned*)(A + ((rA    ) * KA_XST + k0     + 2 * tq) * 2);
            unsigned a1 = *(const unsigned*)(A + ((rA + 8) * KA_XST + k0     + 2 * tq) * 2);
            unsigned a2 = *(const unsigned*)(A + ((rA    ) * KA_XST + k0 + 8 + 2 * tq) * 2);
            unsigned a3 = *(const unsigned*)(A + ((rA + 8) * KA_XST + k0 + 8 + 2 * tq) * 2);
#pragma unroll
            for (int nt = 0; nt < 32; nt++) {
                unsigned b0 = *(const unsigned*)(Bp + ((nt * 8 + gid) * KA_XST + k0     + 2 * tq) * 2);
                unsigned b1 = *(const unsigned*)(Bp + ((nt * 8 + gid) * KA_XST + k0 + 8 + 2 * tq) * 2);
                mma16816(acc[nt], a0, a1, a2, a3, b0, b1);
            }
        }
    }

    float* outp = bx ? d_P2 : d_S;
#pragma unroll
    for (int rh = 0; rh < 2; rh++) {
        const int r = row0 + w * 16 + gid + 8 * rh;
#pragma unroll
        for (int nt = 0; nt < 32; nt++) {
            const int c = nt * 8 + 2 * tq;
            float2 v = make_float2(acc[nt][2 * rh], acc[nt][2 * rh + 1]);
            *(float2*)&outp[(size_t)r * 256 + c] = v;
        }
    }
}

// =====================================================================
// Kernel B (tensor): per CTA = 128 rows (4 nodes x 32 nbrs), N=256, K=64.
//   E = nbr_emb @ W3^T (bf16x3, fp32 reg accum), fused epilogue:
//   g = E + S + bias + mask*P2[adj]; BN1 stats atomics; half2 gated store.
// 256 threads / 8 warps, 1024 CTAs.
// =====================================================================
#define KB_ST 72
#define KB_SM_ADJ  0
#define KB_SM_MASK 512
#define KB_SM_AH   1024
#define KB_SM_AL   (KB_SM_AH + 128 * KB_ST * 2)   // 19456
#define KB_SM_BH   (KB_SM_AL + 128 * KB_ST * 2)   // 37888
#define KB_SM_BL   (KB_SM_BH + 256 * KB_ST * 2)   // 74752
#define KB_SMEM    (KB_SM_BL + 256 * KB_ST * 2)   // 111616
#define KB_SM_DSM  1024                            // reuses A/B region post-mainloop
#define DSM_ST 132

__global__ __launch_bounds__(256) void kB(const float* __restrict__ nbr_emb,
                                          const int* __restrict__ adj,
                                          const float* __restrict__ mask,
                                          const float* __restrict__ bvec) {
    extern __shared__ char sm[];
    const int tid = threadIdx.x;
    const int w   = tid >> 5, lane = tid & 31;
    const int gid = lane >> 2, tq = lane & 3;
    const int tile = blockIdx.x;                    // 0..1023

    // adj/mask for the 128 rows
    if (tid < 128) {
        const int gbn = tile * 4 + (tid >> 5);
        ((int*)  (sm + KB_SM_ADJ ))[tid] = adj [gbn * 32 + (tid & 31)];
        ((float*)(sm + KB_SM_MASK))[tid] = mask[gbn * 32 + (tid & 31)];
    }
    // load + convert A = nbr_emb tile [128][64]
    {
        const float4* xs = (const float4*)(nbr_emb + (size_t)tile * 128 * 64);
#pragma unroll
        for (int i = 0; i < 8; i++) {
            const int idx = tid + i * 256;          // 0..2047
            float4 v = xs[idx];
            const int r = idx >> 4, k4 = (idx & 15) * 4;
            float h0 = __bfloat162float(__float2bfloat16_rn(v.x));
            float h1 = __bfloat162float(__float2bfloat16_rn(v.y));
            float h2 = __bfloat162float(__float2bfloat16_rn(v.z));
            float h3 = __bfloat162float(__float2bfloat16_rn(v.w));
            uint2 hu, lu;
            hu.x = packbf(v.x, v.y);           hu.y = packbf(v.z, v.w);
            lu.x = packbf(v.x - h0, v.y - h1); lu.y = packbf(v.z - h2, v.w - h3);
            *(uint2*)(sm + KB_SM_AH + (r * KB_ST + k4) * 2) = hu;
            *(uint2*)(sm + KB_SM_AL + (r * KB_ST + k4) * 2) = lu;
        }
    }
    // copy W3 hi/lo images [256][64]
    {
        const uint4* sh = (const uint4*)d_W3h;
        const uint4* sl = (const uint4*)d_W3l;
#pragma unroll
        for (int i = 0; i < 8; i++) {
            const int idx = tid + i * 256;          // 0..2047 (8 uint4 per row)
            const int r = idx >> 3, q = idx & 7;
            *(uint4*)(sm + KB_SM_BH + r * (KB_ST * 2) + q * 16) = sh[idx];
            *(uint4*)(sm + KB_SM_BL + r * (KB_ST * 2) + q * 16) = sl[idx];
        }
    }
    __syncthreads();

    float acc[32][4];
#pragma unroll
    for (int nt = 0; nt < 32; nt++)
#pragma unroll
        for (int q = 0; q < 4; q++) acc[nt][q] = 0.f;

    const int rA = w * 16 + gid;
#pragma unroll
    for (int p = 0; p < 3; p++) {
        const char* A  = sm + (p == 2 ? KB_SM_AL : KB_SM_AH);
        const char* Bp = sm + (p == 1 ? KB_SM_BL : KB_SM_BH);
#pragma unroll
        for (int ks = 0; ks < 4; ks++) {
            const int k0 = ks * 16;
            unsigned a0 = *(const unsigned*)(A + ((rA    ) * KB_ST + k0     + 2 * tq) * 2);
            unsigned a1 = *(const unsigned*)(A + ((rA + 8) * KB_ST + k0     + 2 * tq) * 2);
            unsigned a2 = *(const unsigned*)(A + ((rA    ) * KB_ST + k0 + 8 + 2 * tq) * 2);
            unsigned a3 = *(const unsigned*)(A + ((rA + 8) * KB_ST + k0 + 8 + 2 * tq) * 2);
#pragma unroll
            for (int nt = 0; nt < 32; nt++) {
                unsigned b0 = *(const unsigned*)(Bp + ((nt * 8 + gid) * KB_ST + k0     + 2 * tq) * 2);
                unsigned b1 = *(const unsigned*)(Bp + ((nt * 8 + gid) * KB_ST + k0 + 8 + 2 * tq) * 2);
                mma16816(acc[nt], a0, a1, a2, a3, b0, b1);
            }
        }
    }
    __syncthreads();   // A/B SMEM dead; DSM region reuse is now safe

    // Phase 1: fuse epilogue from regs -> half2 DSM stage
    {
        const int*   sadj  = (const int*)  (sm + KB_SM_ADJ);
        const float* smask = (const float*)(sm + KB_SM_MASK);
        unsigned* dsm = (unsigned*)(sm + KB_SM_DSM);
#pragma unroll
        for (int rh = 0; rh < 2; rh++) {
            const int r   = w * 16 + gid + 8 * rh;
            const int gbn = tile * 4 + (r >> 5);
            const int batch = gbn >> 9;
            const float* srow = d_S + (size_t)gbn * 256;
            const float* p2r  = d_P2 + ((size_t)batch * 512 + sadj[r]) * 256;
            const float mk = smask[r];
#pragma unroll
            for (int nt = 0; nt < 16; nt++) {
                const int j = nt * 8 + 2 * tq;
                float2 sA = *(const float2*)&srow[j];
                float2 sB = *(const float2*)&srow[j + 128];
                float2 bA = *(const float2*)&bvec[j];
                float2 bB = *(const float2*)&bvec[j + 128];
                float2 pA = *(const float2*)&p2r[j];
                float2 pB = *(const float2*)&p2r[j + 128];
                float g0 = acc[nt     ][2 * rh    ] + sA.x + bA.x + mk * pA.x;
                float g1 = acc[nt     ][2 * rh + 1] + sA.y + bA.y + mk * pA.y;
                float h0 = acc[nt + 16][2 * rh    ] + sB.x + bB.x + mk * pB.x;
                float h1 = acc[nt + 16][2 * rh + 1] + sB.y + bB.y + mk * pB.y;
                uint2 st;
                st.x = packh(g0, h0);
                st.y = packh(g1, h1);
                *(uint2*)&dsm[r * DSM_ST + j] = st;
            }
        }
    }
    __syncthreads();

    // Phase 2: column pass — BN1 stats + coalesced gated store
    {
        const int j  = tid & 127;
        const int rh = tid >> 7;
        const unsigned* dsm = (const unsigned*)(sm + KB_SM_DSM);
        unsigned* gout = d_gated2u + (size_t)tile * 128 * 128;
        float s0 = 0.f, q0 = 0.f, s1 = 0.f, q1 = 0.f;
#pragma unroll 8
        for (int r = rh * 64; r < rh * 64 + 64; r++) {
            unsigned v = dsm[r * DSM_ST + j];
            __half2 hv = *reinterpret_cast<__half2*>(&v);
            float g = __low2float(hv), h = __high2float(hv);
            s0 += g; q0 = fmaf(g, g, q0);
            s1 += h; q1 = fmaf(h, h, q1);
            gout[r * 128 + j] = v;
        }
        atomicAdd(&d_stats1[j],       s0);
        atomicAdd(&d_stats1[j + 128], s1);
        atomicAdd(&d_stats1[256 + j], q0);
        atomicAdd(&d_stats1[384 + j], q1);
    }
}

// =====================================================================
// Kernel D: BN1 affine + sigmoid*relu, sum over M -> d_nbr; BN2 stats.
// =====================================================================
__global__ __launch_bounds__(128) void kD(const float* __restrict__ gamma_h,
                                          const float* __restrict__ beta_h) {
    const int bn = blockIdx.x;
    const int j  = threadIdx.x;
    const float inv = 1.f / (float)ROWS;

    float mean0 = d_stats1[j] * inv;
    float var0  = d_stats1[256 + j] * inv - mean0 * mean0;
    float sc0   = gamma_h[j] * rsqrtf(var0 + EPS);
    float sh0   = beta_h[j] - mean0 * sc0;

    float mean1 = d_stats1[j + 128] * inv;
    float var1  = d_stats1[384 + j] * inv - mean1 * mean1;
    float sc1   = gamma_h[j + 128] * rsqrtf(var1 + EPS);
    float sh1   = beta_h[j + 128] - mean1 * sc1;

    const unsigned* grow = d_gated2u + (size_t)bn * 32 * 128;
    float acc = 0.f;
#pragma unroll
    for (int m = 0; m < 32; m++) {
        unsigned v = grow[m * 128 + j];
        __half2 hv = *reinterpret_cast<__half2*>(&v);
        float f = fmaf(__low2float(hv),  sc0, sh0);
        float g = fmaf(__high2float(hv), sc1, sh1);
        float sig = 1.f / (1.f + __expf(-f));
        acc = fmaf(sig, fmaxf(g, 0.f), acc);
    }
    d_nbr[bn * 128 + j] = acc;
    atomicAdd(&d_stats2[j],       acc);
    atomicAdd(&d_stats2[128 + j], acc * acc);
}

// =====================================================================
// Kernel F: out = relu(atom_emb + BN2(nbr_sumed))
// =====================================================================
__global__ __launch_bounds__(128) void kF(const float* __restrict__ atom_emb,
                                          const float* __restrict__ gamma_o,
                                          const float* __restrict__ beta_o,
                                          float* __restrict__ out) {
    const int bn = blockIdx.x;
    const int j  = threadIdx.x;
    const float inv = 1.f / (float)BN_ROWS;

    float mean = d_stats2[j] * inv;
    float var  = d_stats2[128 + j] * inv - mean * mean;
    float sc   = gamma_o[j] * rsqrtf(var + EPS);
    float sh   = beta_o[j] - mean * sc;

    float v = atom_emb[bn * 128 + j] + fmaf(d_nbr[bn * 128 + j], sc, sh);
    out[bn * 128 + j] = fmaxf(v, 0.f);
}

// =====================================================================
extern "C" void kernel_launch(void* const* d_in, const int* in_sizes, int n_in,
                              void* d_out, int out_size) {
    (void)in_sizes; (void)n_in; (void)out_size;
    const float* atom_emb = (const float*)d_in[0];
    const float* nbr_emb  = (const float*)d_in[1];
    const int*   adj      = (const int*)d_in[2];   // jax int64 request -> int32 (x64 disabled)
    const float* mask     = (const float*)d_in[3];
    const float* W        = (const float*)d_in[4];
    const float* bvec     = (const float*)d_in[5];
    const float* gamma_h  = (const float*)d_in[6];
    const float* beta_h   = (const float*)d_in[7];
    const float* gamma_o  = (const float*)d_in[8];
    const float* beta_o   = (const float*)d_in[9];
    float* out = (float*)d_out;

    cudaFuncSetAttribute(kA, cudaFuncAttributeMaxDynamicSharedMemorySize, KA_SMEM);
    cudaFuncSetAttribute(kB, cudaFuncAttributeMaxDynamicSharedMemorySize, KB_SMEM);

    kP<<<1,    256>>>(W);
    kA<<<64,   256, KA_SMEM>>>(atom_emb);
    kB<<<1024, 256, KB_SMEM>>>(nbr_emb, adj, mask, bvec);
    kD<<<4096, 128>>>(gamma_h, beta_h);
    kF<<<4096, 128>>>(atom_emb, gamma_o, beta_o, out);
}